// round 13
// baseline (speedup 1.0000x reference)
#include <cuda_runtime.h>
#include <cuda_bf16.h>

#define FULL_MASK 0xFFFFFFFFu

constexpr int B_ROWS     = 16384;
constexpr int SEQ_L      = 50;
constexpr int N_SUBJECTS = 10000;
constexpr int N_ITER     = 13;       // 13 iters x 4 positions per pool = 52 >= 50
constexpr int THREADS    = 256;      // 8 warps
constexpr int ROWS_PER_WARP  = 2;
constexpr int ROWS_PER_BLOCK = 8 * ROWS_PER_WARP;   // 16

// Premultiplied table: row j = escore_j * emb_j as 16 bf16 (32B, one sector).
// escore_j = exp(dot(emb_j, w) + b); escore_0 := 0 -> row 0 all zeros, so
// PAD (idx 0) and out-of-range positions contribute nothing.
// Softmax without max-subtraction is exact: scores are O(0.1)
// (emb ~0.1*N, w ~0.25*N, D=16) -> no fp32 overflow; shift-invariant.
__device__ __align__(128) uint4 g_pm[N_SUBJECTS * 2];
// escore as bf16 (for softmax denominators; served from smem in main kernel)
__device__ __align__(16) unsigned short g_esc[N_SUBJECTS];

__device__ __forceinline__ float dot4(float4 a, float4 b) {
    return a.x * b.x + a.y * b.y + a.z * b.z + a.w * b.w;
}
__device__ __forceinline__ float bf2f(unsigned short h) {
    return __uint_as_float(((unsigned)h) << 16);
}

// ---------------- Prologue: build premult table + escore ----------------
__global__ void __launch_bounds__(256)
tab_kernel(const float* __restrict__ subj_emb,
           const float* __restrict__ attn_w,
           const float* __restrict__ attn_b)
{
    const int j = blockIdx.x * blockDim.x + threadIdx.x;
    if (j >= N_SUBJECTS) return;

    const float4* wp = reinterpret_cast<const float4*>(attn_w);
    const float4 w0 = __ldg(wp + 0), w1 = __ldg(wp + 1),
                 w2 = __ldg(wp + 2), w3 = __ldg(wp + 3);

    const float4* ep = reinterpret_cast<const float4*>(subj_emb) + (size_t)j * 4;
    const float4 e0 = __ldg(ep + 0), e1 = __ldg(ep + 1),
                 e2 = __ldg(ep + 2), e3 = __ldg(ep + 3);

    const float s = dot4(e0, w0) + dot4(e1, w1) + dot4(e2, w2) + dot4(e3, w3)
                  + __ldg(attn_b);
    const float w = (j == 0) ? 0.0f : __expf(s);

    auto pack2 = [](float a, float b) -> unsigned {
        __nv_bfloat162 h = __floats2bfloat162_rn(a, b);
        return *reinterpret_cast<unsigned*>(&h);
    };

    g_pm[j * 2 + 0] = make_uint4(pack2(w*e0.x, w*e0.y), pack2(w*e0.z, w*e0.w),
                                 pack2(w*e1.x, w*e1.y), pack2(w*e1.z, w*e1.w));
    g_pm[j * 2 + 1] = make_uint4(pack2(w*e2.x, w*e2.y), pack2(w*e2.z, w*e2.w),
                                 pack2(w*e3.x, w*e3.y), pack2(w*e3.z, w*e3.w));

    const __nv_bfloat16 hw = __float2bfloat16(w);
    g_esc[j] = *reinterpret_cast<const unsigned short*>(&hw);
}

// ---------------- Main: warp per row, 8 groups x 4 lanes ----------------
// Iteration it: group g (lane>>2) handles position p = it*4 + (g&3) of pool
// (g<4 ? fav : book). Lane chunk c = lane&3 loads 8B (dims 4c..4c+3) of the
// 32B premult row -> ONE LDG.64 covers 4 fav + 4 book positions.
// Denominators come from the 20KB smem bf16 escore table (LDS, no L1tex).
__global__ void __launch_bounds__(THREADS)
scalar_pooler_kernel(
    const float* __restrict__ user_bias,
    const float* __restrict__ item_bias,
    const float* __restrict__ global_bias,
    const int*   __restrict__ user_idx,
    const int*   __restrict__ item_idx,
    const int*   __restrict__ fav,
    const int*   __restrict__ book,
    float*       __restrict__ out)
{
    __shared__ __align__(16) unsigned short s_esc[N_SUBJECTS];
    {
        const uint4* src4 = reinterpret_cast<const uint4*>(g_esc);
        uint4* dst4 = reinterpret_cast<uint4*>(s_esc);
        #pragma unroll
        for (int i = threadIdx.x; i < N_SUBJECTS * 2 / 16; i += THREADS)
            dst4[i] = __ldg(src4 + i);
    }
    __syncthreads();

    const int warp = threadIdx.x >> 5;
    const int lane = threadIdx.x & 31;
    const int posoff = (lane >> 2) & 3;            // position offset in iter
    const int c      = lane & 3;                   // 8B chunk of 32B row
    const bool hi_ok = (lane + 32) < SEQ_L;        // lanes 0..17
    const bool is_fav = (lane < 16);               // groups 0-3

    const char* tabc = reinterpret_cast<const char*>(g_pm) + c * 8;
    const int row0 = blockIdx.x * ROWS_PER_BLOCK + warp * ROWS_PER_WARP;

    #pragma unroll
    for (int r = 0; r < ROWS_PER_WARP; r++) {
        const int row = row0 + r;
        const int* frow = fav  + (size_t)row * SEQ_L;
        const int* brow = book + (size_t)row * SEQ_L;

        // Coalesced raw index preload: lane owns positions lane, lane+32.
        int f_lo = __ldg(frow + lane);
        int f_hi = hi_ok ? __ldg(frow + lane + 32) : 0;
        int b_lo = __ldg(brow + lane);
        int b_hi = hi_ok ? __ldg(brow + lane + 32) : 0;

        // Denominator partials from smem (escore[0] == 0 -> PAD free).
        float su = bf2f(s_esc[f_lo]) + (hi_ok ? bf2f(s_esc[f_hi]) : 0.f);
        float si = bf2f(s_esc[b_lo]) + (hi_ok ? bf2f(s_esc[b_hi]) : 0.f);

        // Pre-shift to byte offsets (row stride 32B).
        f_lo <<= 5;  f_hi <<= 5;  b_lo <<= 5;  b_hi <<= 5;

        float4 acc = make_float4(0.f, 0.f, 0.f, 0.f);  // fav for g<4, book else

        #pragma unroll
        for (int it = 0; it < N_ITER; it++) {
            const int src = ((it < 8) ? it * 4 : (it - 8) * 4) + posoff;
            const int xf = __shfl_sync(FULL_MASK, (it < 8) ? f_lo : f_hi, src);
            const int xb = __shfl_sync(FULL_MASK, (it < 8) ? b_lo : b_hi, src);
            const int off = is_fav ? xf : xb;

            const uint2 v = __ldg(reinterpret_cast<const uint2*>(
                                      tabc + (size_t)(unsigned)off));
            acc.x += __uint_as_float(v.x << 16);
            acc.y += __uint_as_float(v.x & 0xFFFF0000u);
            acc.z += __uint_as_float(v.y << 16);
            acc.w += __uint_as_float(v.y & 0xFFFF0000u);
        }

        // Reduce across the 4 groups of each half (xor 4, 8 stay in-half):
        // lanes 0-15 -> full u chunk c; lanes 16-31 -> full i chunk c.
        #pragma unroll
        for (int off = 4; off <= 8; off <<= 1) {
            acc.x += __shfl_xor_sync(FULL_MASK, acc.x, off);
            acc.y += __shfl_xor_sync(FULL_MASK, acc.y, off);
            acc.z += __shfl_xor_sync(FULL_MASK, acc.z, off);
            acc.w += __shfl_xor_sync(FULL_MASK, acc.w, off);
        }

        // Cross half: bring the other pool's chunk over and dot.
        float4 oth;
        oth.x = __shfl_xor_sync(FULL_MASK, acc.x, 16);
        oth.y = __shfl_xor_sync(FULL_MASK, acc.y, 16);
        oth.z = __shfl_xor_sync(FULL_MASK, acc.z, 16);
        oth.w = __shfl_xor_sync(FULL_MASK, acc.w, 16);

        float rr = dot4(acc, oth);          // per-chunk u.i (dup on both halves)
        rr += __shfl_xor_sync(FULL_MASK, rr, 1);
        rr += __shfl_xor_sync(FULL_MASK, rr, 2);   // lane 0: sum of 4 chunks

        // Denominators: full butterfly.
        #pragma unroll
        for (int off = 16; off; off >>= 1) {
            su += __shfl_xor_sync(FULL_MASK, su, off);
            si += __shfl_xor_sync(FULL_MASK, si, off);
        }

        if (lane == 0) {
            // All-pad row: su/si == 0 -> inv = 0 matches the reference
            // (it pools the all-zero PAD embedding row).
            const float inv_u = (su > 0.f) ? (1.0f / su) : 0.f;
            const float inv_i = (si > 0.f) ? (1.0f / si) : 0.f;
            out[row] = rr * inv_u * inv_i
                     + __ldg(user_bias + __ldg(user_idx + row))
                     + __ldg(item_bias + __ldg(item_idx + row))
                     + __ldg(global_bias);
        }
    }
}

extern "C" void kernel_launch(void* const* d_in, const int* in_sizes, int n_in,
                              void* d_out, int out_size)
{
    const float* subj_emb    = (const float*)d_in[0];
    const float* attn_w      = (const float*)d_in[1];
    const float* attn_b      = (const float*)d_in[2];
    const float* user_bias   = (const float*)d_in[3];
    const float* item_bias   = (const float*)d_in[4];
    const float* global_bias = (const float*)d_in[5];
    const int*   user_idx    = (const int*)d_in[6];
    const int*   item_idx    = (const int*)d_in[7];
    const int*   fav         = (const int*)d_in[8];
    const int*   book        = (const int*)d_in[9];
    float*       out         = (float*)d_out;

    tab_kernel<<<(N_SUBJECTS + 255) / 256, 256>>>(subj_emb, attn_w, attn_b);

    const int blocks = B_ROWS / ROWS_PER_BLOCK;    // 1024
    scalar_pooler_kernel<<<blocks, THREADS>>>(
        user_bias, item_bias, global_bias,
        user_idx, item_idx, fav, book, out);
}